// round 12
// baseline (speedup 1.0000x reference)
#include <cuda_runtime.h>
#include <cstdint>
#include <cstddef>

#define BB 2
#define NN 100
#define HH 800
#define WW 1344
#define PP (HH*WW)          // 1075200 pixels per batch
#define WORDS (PP/32)       // 33600 words per plane
#define Q4S (PP/4)          // 268800 uint4 chunks per plane
#define G 10                // group size
#define NG (NN/G)           // 10 groups
#define HSIZE (1<<G)        // 1024 histogram buckets
#define NSEM 134
#define TPB 256
#define WBLK ((WORDS + TPB - 1)/TPB)   // 132

#define MASK_ELEMS (BB*NN*PP)
#define SEM_ELEMS  (BB*PP)

// Bit layout (permuted, consistent everywhere):
//   word w = B*256 + wp*32 + lane
//   bit (4j+k) of word w  <->  component k of uint4 q = B*2048 + wp*256 + j*32 + lane

// ---------------- device state ----------------------------------------------
__device__ uint32_t g_planes[BB][NN][WORDS];
__device__ int      g_order[BB][NN];
__device__ float    g_sscore[BB][NN];
__device__ int      g_scls[BB][NN];
__device__ int      g_area[BB][NN];
__device__ int      g_hist[BB][NG][HSIZE];
__device__ int      g_interA[BB][NG][G];
__device__ unsigned g_ticket[BB][NG+1];
__device__ int      g_flag[BB][NG+1];
__device__ int      g_keptmask[BB][NG];
__device__ int      g_nkept[BB];
__device__ int      g_kept_rank[BB][NN];
__device__ int      g_kept_val[BB][NN];
__device__ int      g_next_iid[BB];
__device__ int      g_cls_counts[BB][NSEM];
// transport flags
__device__ int      g_a_is_cls;
__device__ int      g_cls_f32;
__device__ int      g_sem_f32;
__device__ int      g_mask_byte;

// ---------------- init -------------------------------------------------------
__global__ void k_init() {
    int idx = blockIdx.x * blockDim.x + threadIdx.x;
    int stride = gridDim.x * blockDim.x;
    int* h = &g_hist[0][0][0];
    for (int i = idx; i < BB*NG*HSIZE; i += stride) h[i] = 0;
    int* ia = &g_interA[0][0][0];
    for (int i = idx; i < BB*NG*G; i += stride) ia[i] = 0;
    unsigned* tk = &g_ticket[0][0];
    int* fl = &g_flag[0][0];
    for (int i = idx; i < BB*(NG+1); i += stride) { tk[i] = 0u; fl[i] = 0; }
    int* km = &g_keptmask[0][0];
    for (int i = idx; i < BB*NG; i += stride) km[i] = 0;
    int* ar = &g_area[0][0];
    for (int i = idx; i < BB*NN; i += stride) ar[i] = 0;
    int* cc = &g_cls_counts[0][0];
    for (int i = idx; i < BB*NSEM; i += stride) cc[i] = 0;
    if (idx < BB) { g_nkept[idx] = 0; g_next_iid[idx] = 1; }
}

// ---------------- prep: transport detection + stable sort (one block) -------
__device__ __forceinline__ bool int_in(unsigned int raw, int lo, int hi) {
    int v = (int)raw; return v >= lo && v < hi;
}
__device__ __forceinline__ bool f32_in(unsigned int raw, int lo, int hi) {
    float f = __uint_as_float(raw);
    if (!(f >= (float)lo && f < (float)hi)) return false;
    return floorf(f) == f;
}

__global__ void k_prep(const unsigned int* __restrict__ pa,
                       const unsigned int* __restrict__ pb,
                       const unsigned int* __restrict__ sem,
                       const unsigned int* __restrict__ masks) {
    __shared__ int f_ai, f_af, f_bi, f_bf, f_si, f_sf, f_w;
    __shared__ float ss[BB][NN];
    int t = threadIdx.x;
    if (t == 0) { f_ai=1; f_af=1; f_bi=1; f_bf=1; f_si=1; f_sf=1; f_w=1; }
    __syncthreads();
    if (t < BB*NN) {
        unsigned int va = pa[t], vb = pb[t];
        if (!int_in(va, 0, 80)) f_ai = 0;
        if (!f32_in(va, 0, 80)) f_af = 0;
        if (!int_in(vb, 0, 80)) f_bi = 0;
        if (!f32_in(vb, 0, 80)) f_bf = 0;
    }
    #pragma unroll
    for (int k = 0; k < 4; k++) {
        int i = (t + 256*k) * (SEM_ELEMS/1024);
        unsigned int v = sem[i];
        if (!int_in(v, 0, NSEM)) f_si = 0;
        if (!f32_in(v, 0, NSEM)) f_sf = 0;
    }
    #pragma unroll
    for (int k = 0; k < 4; k++) {
        unsigned int v = masks[t + 256*k];
        if (!(v == 0u || v == 1u || v == 0x3F800000u)) f_w = 0;
    }
    __syncthreads();
    int a_cls = (f_ai | f_af);
    int clsf  = a_cls ? (f_af && !f_ai) : (f_bf && !f_bi);
    if (t == 0) {
        g_a_is_cls = a_cls;
        g_cls_f32  = clsf;
        g_sem_f32  = (f_sf && !f_si);
        g_mask_byte = f_w ? 0 : 1;
    }
    const unsigned int* scores = a_cls ? pb : pa;
    const unsigned int* cls    = a_cls ? pa : pb;
    for (int i = t; i < BB*NN; i += blockDim.x)
        ss[i/NN][i%NN] = __uint_as_float(scores[i]);
    __syncthreads();
    for (int idx = t; idx < BB*NN; idx += blockDim.x) {
        int b = idx / NN, i = idx % NN;
        float si = ss[b][i];
        int r = 0;
        #pragma unroll 4
        for (int j = 0; j < NN; j++) {
            float sj = ss[b][j];
            r += (sj > si) || (sj == si && j < i);
        }
        unsigned int rawc = cls[b*NN + i];
        int c = clsf ? (int)__uint_as_float(rawc) : (int)rawc;
        g_order[b][r]  = i;
        g_sscore[b][r] = si;
        g_scls[b][r]   = c;
    }
}

// ---------------- pack one group's planes into registers --------------------
__device__ __forceinline__ void pack_group(
    const unsigned int* __restrict__ masks, int mask_byte,
    int b, int g, int Bx, int wp, int lane, bool valid, uint32_t pw[G])
{
    #pragma unroll
    for (int i = 0; i < G; i++) pw[i] = 0;
    if (!valid) return;
    int qbase = Bx*2048 + wp*256 + lane;
    #pragma unroll
    for (int i = 0; i < G; i++) {
        int r = g*G + i;
        if (g_sscore[b][r] < 0.5f) continue;   // non-candidate: plane stays 0
        if (!mask_byte) {
            const uint4* mp = (const uint4*)masks + (size_t)(b*NN + g_order[b][r]) * (size_t)Q4S;
            uint32_t acc = 0;
            #pragma unroll
            for (int j = 0; j < 8; j++) {
                uint4 x = mp[qbase + j*32];
                uint32_t nib = ((x.x | (x.x >> 23)) & 1u)
                             | (((x.y | (x.y >> 23)) & 1u) << 1)
                             | (((x.z | (x.z >> 23)) & 1u) << 2)
                             | (((x.w | (x.w >> 23)) & 1u) << 3);
                acc |= nib << (4*j);
            }
            pw[i] = acc;
        } else {
            const unsigned int* bp = (const unsigned int*)
                ((const unsigned char*)masks + (size_t)(b*NN + g_order[b][r]) * (size_t)PP);
            uint32_t acc = 0;
            #pragma unroll
            for (int j = 0; j < 8; j++) {
                unsigned int v = bp[qbase + j*32];
                uint32_t nib = (v | (v >> 7) | (v >> 14) | (v >> 21)) & 0xFu;
                acc |= nib << (4*j);
            }
            pw[i] = acc;
        }
    }
}

// store planes + accumulate areas for a freshly packed group
__device__ __forceinline__ void store_group(
    int b, int g, int w, bool valid, int lane, const uint32_t pw[G])
{
    #pragma unroll
    for (int i = 0; i < G; i++) {
        if (valid && pw[i]) g_planes[b][g*G+i][w] = pw[i];
        else if (valid) g_planes[b][g*G+i][w] = 0u;
        int a = __popc(pw[i]);
        #pragma unroll
        for (int o = 16; o; o >>= 1) a += __shfl_down_sync(0xffffffffu, a, o);
        if (lane == 0 && a) atomicAdd(&g_area[b][g*G+i], a);
    }
}

// ---------------- fused: pack-pipelined phases + stuff hist + final ---------
__global__ void __launch_bounds__(TPB, 2)
k_run(const unsigned int* __restrict__ masks,
      const unsigned int* __restrict__ sem, uint4* __restrict__ out) {
    int b = blockIdx.y;
    int t = threadIdx.x, lane = t & 31, wp = t >> 5;
    int w = blockIdx.x * TPB + t;
    bool valid = (w < WORDS);
    int mask_byte = g_mask_byte;
    uint32_t c = 0;                       // claimed word (register)

    __shared__ int s_hist[TPB/32][HSIZE]; // per-warp histograms (32KB)
    __shared__ int s_a[G];
    __shared__ unsigned s_old;
    __shared__ int s_km;
    __shared__ int s_nk;
    __shared__ int s_kr[NN];
    __shared__ int s_kv[NN];
    __shared__ unsigned s_sval[NSEM];
    int* s_cnt = &s_hist[0][0];           // alias (phases done before stuff)

    uint32_t pw[G];
    // prologue: pack group 0 if live
    if (g_sscore[b][0] >= 0.5f) {
        pack_group(masks, mask_byte, b, 0, blockIdx.x, wp, lane, valid, pw);
        store_group(b, 0, w, valid, lane, pw);
    } else {
        #pragma unroll
        for (int i = 0; i < G; i++) pw[i] = 0;
    }

    // ================= live phases (pack of g+1 pipelined) ==================
    for (int g = 0; g < NG; g++) {
        if (g_sscore[b][g*G] < 0.5f) break;     // dead prefix boundary

        for (int i = t; i < (TPB/32)*HSIZE; i += TPB) (&s_hist[0][0])[i] = 0;
        if (t < G) s_a[t] = 0;
        __syncthreads();

        int a_loc[G];
        #pragma unroll
        for (int i = 0; i < G; i++) a_loc[i] = __popc(pw[i] & c);

        uint32_t u = valid ? ~c : 0u;
        while (u) {
            int p = __ffs(u) - 1; u &= u - 1;
            int pat = 0;
            #pragma unroll
            for (int i = 0; i < G; i++) pat |= (int)((pw[i] >> p) & 1u) << i;
            if (pat) atomicAdd(&s_hist[wp][pat], 1);
        }
        #pragma unroll
        for (int i = 0; i < G; i++) {
            int v = a_loc[i];
            #pragma unroll
            for (int o = 16; o; o >>= 1) v += __shfl_down_sync(0xffffffffu, v, o);
            if (lane == 0 && v) atomicAdd(&s_a[i], v);
        }
        __syncthreads();
        for (int i = t; i < HSIZE; i += TPB) {
            int s = 0;
            #pragma unroll
            for (int k = 0; k < TPB/32; k++) s += s_hist[k][i];
            if (s) atomicAdd(&g_hist[b][g][i], s);
        }
        if (t < G && s_a[t]) atomicAdd(&g_interA[b][g][t], s_a[t]);
        __syncthreads();
        if (t == 0) {
            __threadfence();
            s_old = atomicAdd(&g_ticket[b][g], 1u);
        }
        __syncthreads();
        if (s_old == gridDim.x - 1) {
            if (wp == 0) {
                const int HL = HSIZE/32;
                int h[HL];
                #pragma unroll
                for (int k = 0; k < HL; k++) h[k] = __ldcg(&g_hist[b][g][lane*HL + k]);
                int keptm = 0;
                int iid = __ldcg(&g_next_iid[b]);
                int nk  = __ldcg(&g_nkept[b]);
                for (int i = 0; i < G; i++) {
                    int r = g*G + i;
                    float s  = g_sscore[b][r];
                    int area = __ldcg(&g_area[b][r]);
                    int inter = __ldcg(&g_interA[b][g][i]);
                    int loc = 0;
                    #pragma unroll
                    for (int k = 0; k < HL; k++) {
                        int pat = lane*HL + k;
                        if (((pat >> i) & 1) && (pat & keptm)) loc += h[k];
                    }
                    #pragma unroll
                    for (int o = 16; o; o >>= 1) loc += __shfl_xor_sync(0xffffffffu, loc, o);
                    inter += loc;
                    bool keep = (s >= 0.5f) && (area > 0) &&
                                ((float)inter <= 0.5f * (float)area);
                    if (keep) {
                        if (lane == 0) {
                            g_kept_rank[b][nk] = r;
                            g_kept_val[b][nk]  = g_scls[b][r] + iid * 1000;
                        }
                        keptm |= 1 << i;
                        iid++; nk++;
                    }
                }
                if (lane == 0) {
                    g_keptmask[b][g] = keptm;
                    g_next_iid[b] = iid;
                    g_nkept[b] = nk;
                    __threadfence();
                    atomicExch(&g_flag[b][g], 1);
                }
            }
            __syncthreads();
        }

        // ---- pack next group while waiting for the decision flag ----
        bool packnext = (g+1 < NG) && (g_sscore[b][(g+1)*G] >= 0.5f);
        if (packnext) {
            pack_group(masks, mask_byte, b, g+1, blockIdx.x, wp, lane, valid, pw);
            store_group(b, g+1, w, valid, lane, pw);
        } else {
            #pragma unroll
            for (int i = 0; i < G; i++) pw[i] = 0;
        }

        if (t == 0) {
            while (__ldcg(&g_flag[b][g]) == 0) __nanosleep(64);
            __threadfence();
            s_km = __ldcg(&g_keptmask[b][g]);
        }
        __syncthreads();
        // claimed update: re-read this block's own kept plane words (L1/L2 hot)
        if (valid) {
            int km = s_km;
            while (km) { int i = __ffs(km) - 1; km &= km - 1; c |= g_planes[b][g*G+i][w]; }
        }
        __syncthreads();       // protect s_hist reuse next iteration
    }

    // ================= stuff histogram (uses register claimed c) =============
    int semf = g_sem_f32;
    for (int i = t; i < NSEM; i += TPB) s_cnt[i] = 0;
    __syncthreads();
    const uint4* sp4 = (const uint4*)(sem + (size_t)b * PP);
    if (valid && c != 0xFFFFFFFFu) {
        #pragma unroll
        for (int j = 0; j < 8; j++) {
            uint32_t nibc = (c >> (4*j)) & 0xFu;
            if (nibc != 0xFu) {
                int q = blockIdx.x*2048 + wp*256 + j*32 + lane;
                uint4 x = sp4[q];
                unsigned int vv[4] = {x.x, x.y, x.z, x.w};
                #pragma unroll
                for (int k = 0; k < 4; k++) {
                    if (!((nibc >> k) & 1u)) {
                        int s = semf ? (int)__uint_as_float(vv[k]) : (int)vv[k];
                        if (s >= 0 && s < NSEM) atomicAdd(&s_cnt[s], 1);
                    }
                }
            }
        }
    }
    __syncthreads();
    for (int i = t; i < NSEM; i += TPB)
        if (s_cnt[i]) atomicAdd(&g_cls_counts[b][i], s_cnt[i]);

    // barrier: all counts in
    __threadfence();
    __syncthreads();
    if (t == 0) s_old = atomicAdd(&g_ticket[b][NG], 1u);
    __syncthreads();
    if (s_old == gridDim.x - 1) {
        if (t == 0) { __threadfence(); atomicExch(&g_flag[b][NG], 1); }
        __syncthreads();
    }
    if (t == 0) {
        while (__ldcg(&g_flag[b][NG]) == 0) __nanosleep(64);
        __threadfence();
        s_nk = __ldcg(&g_nkept[b]);
    }
    __syncthreads();
    int nk = s_nk;
    for (int i = t; i < NSEM; i += TPB) {
        int cnt = __ldcg(&g_cls_counts[b][i]);
        int v = (i < NSEM-1 && cnt >= 4096) ? (i + 80) : 0;
        s_sval[i] = (unsigned int)__float_as_int((float)v);
    }
    for (int i = t; i < nk; i += TPB) {
        s_kr[i] = __ldcg(&g_kept_rank[b][i]);
        s_kv[i] = __ldcg(&g_kept_val[b][i]);
    }
    __syncthreads();

    // ================= final write (float32-encoded output) ==================
    if (!valid) return;
    uint4* op4 = out + (size_t)b * Q4S;
    #pragma unroll
    for (int j = 0; j < 8; j++) {
        int q = blockIdx.x*2048 + wp*256 + j*32 + lane;
        uint32_t nibc = (c >> (4*j)) & 0xFu;
        unsigned int vals[4];
        uint32_t rem = nibc;
        for (int k = 0; k < nk && rem; k++) {
            uint32_t pm = ((g_planes[b][s_kr[k]][w] >> (4*j)) & 0xFu) & rem;
            if (pm) {
                unsigned int fv = (unsigned int)__float_as_int((float)s_kv[k]);
                rem ^= pm;
                while (pm) { int p = __ffs(pm) - 1; pm &= pm - 1; vals[p] = fv; }
            }
        }
        uint32_t un = (~nibc) & 0xFu;
        if (un) {
            uint4 x = sp4[q];
            unsigned int vv[4] = {x.x, x.y, x.z, x.w};
            while (un) {
                int p = __ffs(un) - 1; un &= un - 1;
                int s = semf ? (int)__uint_as_float(vv[p]) : (int)vv[p];
                vals[p] = (s >= 0 && s < NSEM) ? s_sval[s]
                          : (unsigned int)__float_as_int(0.0f);
            }
        }
        op4[q] = make_uint4(vals[0], vals[1], vals[2], vals[3]);
    }
}

// ---------------- launch -----------------------------------------------------
extern "C" void kernel_launch(void* const* d_in, const int* in_sizes, int n_in,
                              void* d_out, int out_size) {
    const void* masks = nullptr;
    const void* sem   = nullptr;
    const void* smallA = nullptr;
    const void* smallB = nullptr;
    for (int i = 0; i < n_in; i++) {
        if (in_sizes[i] == MASK_ELEMS)      masks = d_in[i];
        else if (in_sizes[i] == SEM_ELEMS)  sem   = d_in[i];
        else if (in_sizes[i] == BB*NN) {
            if (!smallA) smallA = d_in[i]; else smallB = d_in[i];
        }
    }
    if (!masks)  masks  = d_in[0];
    if (!smallA) smallA = d_in[1];
    if (!smallB) smallB = d_in[2];
    if (!sem)    sem    = d_in[3];

    k_init<<<128, 256>>>();
    k_prep<<<1, 256>>>((const unsigned int*)smallA, (const unsigned int*)smallB,
                       (const unsigned int*)sem, (const unsigned int*)masks);
    k_run<<<dim3(WBLK, BB), TPB>>>((const unsigned int*)masks,
                                   (const unsigned int*)sem, (uint4*)d_out);
}

// round 13
// speedup vs baseline: 1.0070x; 1.0070x over previous
#include <cuda_runtime.h>
#include <cstdint>
#include <cstddef>

#define BB 2
#define NN 100
#define HH 800
#define WW 1344
#define PP (HH*WW)          // 1075200 pixels per batch
#define WORDS (PP/32)       // 33600 words per plane
#define Q4S (PP/4)          // 268800 uint4 chunks per plane
#define G 10                // group size
#define NG (NN/G)           // 10 groups
#define HSIZE (1<<G)        // 1024 histogram buckets
#define NSEM 134
#define TPB 256
#define WBLK ((WORDS + TPB - 1)/TPB)   // 132

#define MASK_ELEMS (BB*NN*PP)
#define SEM_ELEMS  (BB*PP)

// Bit layout (permuted, consistent everywhere):
//   word w = B*256 + wp*32 + lane
//   bit (4j+k) of word w  <->  component k of uint4 q = B*2048 + wp*256 + j*32 + lane

// ---------------- device state ----------------------------------------------
__device__ uint32_t g_planes[BB][NN][WORDS];
__device__ int      g_order[BB][NN];
__device__ float    g_sscore[BB][NN];
__device__ int      g_scls[BB][NN];
__device__ int      g_area[BB][NN];
__device__ int      g_hist[BB][NG][HSIZE];
__device__ int      g_interA[BB][NG][G];
__device__ unsigned g_ticket[BB][NG+1];
__device__ int      g_flag[BB][NG+1];
__device__ int      g_keptmask[BB][NG];
__device__ int      g_nkept[BB];
__device__ int      g_kept_rank[BB][NN];
__device__ int      g_kept_val[BB][NN];
__device__ int      g_next_iid[BB];
__device__ int      g_cls_counts[BB][NSEM];
__device__ int      g_pack_cnt[BB][NG][WBLK];   // per (batch, group, word-block) pack completion
// transport flags
__device__ int      g_a_is_cls;
__device__ int      g_cls_f32;
__device__ int      g_sem_f32;
__device__ int      g_mask_byte;

// ---------------- init -------------------------------------------------------
__global__ void k_init() {
    int idx = blockIdx.x * blockDim.x + threadIdx.x;
    int stride = gridDim.x * blockDim.x;
    int* h = &g_hist[0][0][0];
    for (int i = idx; i < BB*NG*HSIZE; i += stride) h[i] = 0;
    int* ia = &g_interA[0][0][0];
    for (int i = idx; i < BB*NG*G; i += stride) ia[i] = 0;
    unsigned* tk = &g_ticket[0][0];
    int* fl = &g_flag[0][0];
    for (int i = idx; i < BB*(NG+1); i += stride) { tk[i] = 0u; fl[i] = 0; }
    int* km = &g_keptmask[0][0];
    for (int i = idx; i < BB*NG; i += stride) km[i] = 0;
    int* ar = &g_area[0][0];
    for (int i = idx; i < BB*NN; i += stride) ar[i] = 0;
    int* cc = &g_cls_counts[0][0];
    for (int i = idx; i < BB*NSEM; i += stride) cc[i] = 0;
    int* pc = &g_pack_cnt[0][0][0];
    for (int i = idx; i < BB*NG*WBLK; i += stride) pc[i] = 0;
    if (idx < BB) { g_nkept[idx] = 0; g_next_iid[idx] = 1; }
}

// ---------------- prep: transport detection + stable sort (one block) -------
__device__ __forceinline__ bool int_in(unsigned int raw, int lo, int hi) {
    int v = (int)raw; return v >= lo && v < hi;
}
__device__ __forceinline__ bool f32_in(unsigned int raw, int lo, int hi) {
    float f = __uint_as_float(raw);
    if (!(f >= (float)lo && f < (float)hi)) return false;
    return floorf(f) == f;
}

__global__ void k_prep(const unsigned int* __restrict__ pa,
                       const unsigned int* __restrict__ pb,
                       const unsigned int* __restrict__ sem,
                       const unsigned int* __restrict__ masks) {
    __shared__ int f_ai, f_af, f_bi, f_bf, f_si, f_sf, f_w;
    __shared__ float ss[BB][NN];
    int t = threadIdx.x;
    if (t == 0) { f_ai=1; f_af=1; f_bi=1; f_bf=1; f_si=1; f_sf=1; f_w=1; }
    __syncthreads();
    if (t < BB*NN) {
        unsigned int va = pa[t], vb = pb[t];
        if (!int_in(va, 0, 80)) f_ai = 0;
        if (!f32_in(va, 0, 80)) f_af = 0;
        if (!int_in(vb, 0, 80)) f_bi = 0;
        if (!f32_in(vb, 0, 80)) f_bf = 0;
    }
    #pragma unroll
    for (int k = 0; k < 4; k++) {
        int i = (t + 256*k) * (SEM_ELEMS/1024);
        unsigned int v = sem[i];
        if (!int_in(v, 0, NSEM)) f_si = 0;
        if (!f32_in(v, 0, NSEM)) f_sf = 0;
    }
    #pragma unroll
    for (int k = 0; k < 4; k++) {
        unsigned int v = masks[t + 256*k];
        if (!(v == 0u || v == 1u || v == 0x3F800000u)) f_w = 0;
    }
    __syncthreads();
    int a_cls = (f_ai | f_af);
    int clsf  = a_cls ? (f_af && !f_ai) : (f_bf && !f_bi);
    if (t == 0) {
        g_a_is_cls = a_cls;
        g_cls_f32  = clsf;
        g_sem_f32  = (f_sf && !f_si);
        g_mask_byte = f_w ? 0 : 1;
    }
    const unsigned int* scores = a_cls ? pb : pa;
    const unsigned int* cls    = a_cls ? pa : pb;
    for (int i = t; i < BB*NN; i += blockDim.x)
        ss[i/NN][i%NN] = __uint_as_float(scores[i]);
    __syncthreads();
    for (int idx = t; idx < BB*NN; idx += blockDim.x) {
        int b = idx / NN, i = idx % NN;
        float si = ss[b][i];
        int r = 0;
        #pragma unroll 4
        for (int j = 0; j < NN; j++) {
            float sj = ss[b][j];
            r += (sj > si) || (sj == si && j < i);
        }
        unsigned int rawc = cls[b*NN + i];
        int c = clsf ? (int)__uint_as_float(rawc) : (int)rawc;
        g_order[b][r]  = i;
        g_sscore[b][r] = si;
        g_scls[b][r]   = c;
    }
}

// ---------------- pack (rank-major retirement; signals completion) ----------
// grid = (WBLK, BB, NN): bid = x + b*WBLK + r*WBLK*BB  => rank 0 blocks first.
__global__ void k_pack(const unsigned int* __restrict__ masks) {
    int b = blockIdx.y, r = blockIdx.z;
    int t = threadIdx.x, lane = t & 31, wp = t >> 5;
    bool cand = (g_sscore[b][r] >= 0.5f);
    int orig = g_order[b][r];
    int w = blockIdx.x * 256 + t;
    bool valid = (w < WORDS);
    uint32_t word = 0;

    if (!g_mask_byte) {
        const uint4* mp = (const uint4*)(masks + (size_t)(b*NN + orig) * PP);
        if (cand && valid) {
            #pragma unroll
            for (int j = 0; j < 8; j++) {
                int q = blockIdx.x*2048 + wp*256 + j*32 + lane;  // coalesced
                uint4 x = mp[q];
                // wire-agnostic 0/1 test: works for int 1 and float 1.0f (bit23)
                uint32_t nib = ((x.x | (x.x >> 23)) & 1u)
                             | (((x.y | (x.y >> 23)) & 1u) << 1)
                             | (((x.z | (x.z >> 23)) & 1u) << 2)
                             | (((x.w | (x.w >> 23)) & 1u) << 3);
                word |= nib << (4*j);
            }
        }
    } else {
        const unsigned int* bp = (const unsigned int*)((const unsigned char*)masks
                                   + (size_t)(b*NN + orig) * PP);
        if (cand && valid) {
            #pragma unroll
            for (int j = 0; j < 8; j++) {
                int q = blockIdx.x*2048 + wp*256 + j*32 + lane;
                unsigned int v = bp[q];
                uint32_t nib = (v | (v >> 7) | (v >> 14) | (v >> 21)) & 0xFu;
                word |= nib << (4*j);
            }
        }
    }
    if (valid) g_planes[b][r][w] = word;

    int myarea = __popc(word);
    #pragma unroll
    for (int o = 16; o; o >>= 1) myarea += __shfl_down_sync(0xffffffffu, myarea, o);
    __shared__ int sa[TPB/32];
    if (lane == 0) sa[wp] = myarea;
    __syncthreads();
    if (t == 0) {
        int s = 0;
        #pragma unroll
        for (int k = 0; k < TPB/32; k++) s += sa[k];
        if (s) atomicAdd(&g_area[b][r], s);
        __threadfence();
        atomicAdd(&g_pack_cnt[b][r/G][blockIdx.x], 1);   // signal this window done
    }
}

// ---------------- fused: live phases + stuff hist + final write -------------
// Identical to R11's proven k_run, plus a per-phase wait on pack counters.
__global__ void __launch_bounds__(TPB, 2)
k_run(const unsigned int* __restrict__ sem, uint4* __restrict__ out) {
    int b = blockIdx.y;
    int t = threadIdx.x, lane = t & 31, wp = t >> 5;
    int w = blockIdx.x * TPB + t;
    bool valid = (w < WORDS);
    uint32_t c = 0;                       // claimed word (register)

    __shared__ int s_hist[TPB/32][HSIZE]; // per-warp histograms (32KB)
    __shared__ int s_a[G];
    __shared__ unsigned s_old;
    __shared__ int s_km;
    __shared__ int s_nk;
    __shared__ int s_kr[NN];
    __shared__ int s_kv[NN];
    __shared__ unsigned s_sval[NSEM];
    int* s_cnt = &s_hist[0][0];           // alias (phases done before stuff)

    // ================= live phases =================
    for (int g = 0; g < NG; g++) {
        if (g_sscore[b][g*G] < 0.5f) break;     // dead prefix boundary

        // wait until pack finished THIS block's word window for group g
        if (t == 0) {
            while (__ldcg(&g_pack_cnt[b][g][blockIdx.x]) < G) __nanosleep(128);
            __threadfence();
        }
        __syncthreads();

        for (int i = t; i < (TPB/32)*HSIZE; i += TPB) (&s_hist[0][0])[i] = 0;
        if (t < G) s_a[t] = 0;
        __syncthreads();

        uint32_t pw[G];
        #pragma unroll
        for (int i = 0; i < G; i++) pw[i] = valid ? g_planes[b][g*G+i][w] : 0u;

        int a_loc[G];
        #pragma unroll
        for (int i = 0; i < G; i++) a_loc[i] = __popc(pw[i] & c);

        uint32_t u = valid ? ~c : 0u;
        while (u) {
            int p = __ffs(u) - 1; u &= u - 1;
            int pat = 0;
            #pragma unroll
            for (int i = 0; i < G; i++) pat |= (int)((pw[i] >> p) & 1u) << i;
            if (pat) atomicAdd(&s_hist[wp][pat], 1);
        }
        #pragma unroll
        for (int i = 0; i < G; i++) {
            int v = a_loc[i];
            #pragma unroll
            for (int o = 16; o; o >>= 1) v += __shfl_down_sync(0xffffffffu, v, o);
            if (lane == 0 && v) atomicAdd(&s_a[i], v);
        }
        __syncthreads();
        for (int i = t; i < HSIZE; i += TPB) {
            int s = 0;
            #pragma unroll
            for (int k = 0; k < TPB/32; k++) s += s_hist[k][i];
            if (s) atomicAdd(&g_hist[b][g][i], s);
        }
        if (t < G && s_a[t]) atomicAdd(&g_interA[b][g][t], s_a[t]);
        __syncthreads();
        if (t == 0) {
            __threadfence();
            s_old = atomicAdd(&g_ticket[b][g], 1u);
        }
        __syncthreads();
        if (s_old == gridDim.x - 1) {
            if (wp == 0) {
                const int HL = HSIZE/32;
                int h[HL];
                #pragma unroll
                for (int k = 0; k < HL; k++) h[k] = __ldcg(&g_hist[b][g][lane*HL + k]);
                int keptm = 0;
                int iid = __ldcg(&g_next_iid[b]);
                int nk  = __ldcg(&g_nkept[b]);
                for (int i = 0; i < G; i++) {
                    int r = g*G + i;
                    float s  = g_sscore[b][r];
                    int area = __ldcg(&g_area[b][r]);
                    int inter = __ldcg(&g_interA[b][g][i]);
                    int loc = 0;
                    #pragma unroll
                    for (int k = 0; k < HL; k++) {
                        int pat = lane*HL + k;
                        if (((pat >> i) & 1) && (pat & keptm)) loc += h[k];
                    }
                    #pragma unroll
                    for (int o = 16; o; o >>= 1) loc += __shfl_xor_sync(0xffffffffu, loc, o);
                    inter += loc;
                    bool keep = (s >= 0.5f) && (area > 0) &&
                                ((float)inter <= 0.5f * (float)area);
                    if (keep) {
                        if (lane == 0) {
                            g_kept_rank[b][nk] = r;
                            g_kept_val[b][nk]  = g_scls[b][r] + iid * 1000;
                        }
                        keptm |= 1 << i;
                        iid++; nk++;
                    }
                }
                if (lane == 0) {
                    g_keptmask[b][g] = keptm;
                    g_next_iid[b] = iid;
                    g_nkept[b] = nk;
                    __threadfence();
                    atomicExch(&g_flag[b][g], 1);
                }
            }
            __syncthreads();
        }
        if (t == 0) {
            while (__ldcg(&g_flag[b][g]) == 0) __nanosleep(64);
            __threadfence();
            s_km = __ldcg(&g_keptmask[b][g]);
        }
        __syncthreads();
        int km = s_km;
        #pragma unroll
        for (int i = 0; i < G; i++)
            if ((km >> i) & 1) c |= pw[i];
        __syncthreads();       // protect s_hist reuse next iteration
    }

    // ================= stuff histogram (uses register claimed c) =============
    int semf = g_sem_f32;
    for (int i = t; i < NSEM; i += TPB) s_cnt[i] = 0;
    __syncthreads();
    const uint4* sp4 = (const uint4*)(sem + (size_t)b * PP);
    if (valid && c != 0xFFFFFFFFu) {
        #pragma unroll
        for (int j = 0; j < 8; j++) {
            uint32_t nibc = (c >> (4*j)) & 0xFu;
            if (nibc != 0xFu) {
                int q = blockIdx.x*2048 + wp*256 + j*32 + lane;
                uint4 x = sp4[q];
                unsigned int vv[4] = {x.x, x.y, x.z, x.w};
                #pragma unroll
                for (int k = 0; k < 4; k++) {
                    if (!((nibc >> k) & 1u)) {
                        int s = semf ? (int)__uint_as_float(vv[k]) : (int)vv[k];
                        if (s >= 0 && s < NSEM) atomicAdd(&s_cnt[s], 1);
                    }
                }
            }
        }
    }
    __syncthreads();
    for (int i = t; i < NSEM; i += TPB)
        if (s_cnt[i]) atomicAdd(&g_cls_counts[b][i], s_cnt[i]);

    // barrier: all counts in
    __threadfence();
    __syncthreads();
    if (t == 0) s_old = atomicAdd(&g_ticket[b][NG], 1u);
    __syncthreads();
    if (s_old == gridDim.x - 1) {
        if (t == 0) { __threadfence(); atomicExch(&g_flag[b][NG], 1); }
        __syncthreads();
    }
    if (t == 0) {
        while (__ldcg(&g_flag[b][NG]) == 0) __nanosleep(64);
        __threadfence();
        s_nk = __ldcg(&g_nkept[b]);
    }
    __syncthreads();
    int nk = s_nk;
    for (int i = t; i < NSEM; i += TPB) {
        int cnt = __ldcg(&g_cls_counts[b][i]);
        int v = (i < NSEM-1 && cnt >= 4096) ? (i + 80) : 0;
        s_sval[i] = (unsigned int)__float_as_int((float)v);
    }
    for (int i = t; i < nk; i += TPB) {
        s_kr[i] = __ldcg(&g_kept_rank[b][i]);
        s_kv[i] = __ldcg(&g_kept_val[b][i]);
    }
    __syncthreads();

    // ================= final write (float32-encoded output) ==================
    if (!valid) return;
    uint4* op4 = out + (size_t)b * Q4S;
    #pragma unroll
    for (int j = 0; j < 8; j++) {
        int q = blockIdx.x*2048 + wp*256 + j*32 + lane;
        uint32_t nibc = (c >> (4*j)) & 0xFu;
        unsigned int vals[4];
        uint32_t rem = nibc;
        for (int k = 0; k < nk && rem; k++) {
            uint32_t pm = ((g_planes[b][s_kr[k]][w] >> (4*j)) & 0xFu) & rem;
            if (pm) {
                unsigned int fv = (unsigned int)__float_as_int((float)s_kv[k]);
                rem ^= pm;
                while (pm) { int p = __ffs(pm) - 1; pm &= pm - 1; vals[p] = fv; }
            }
        }
        uint32_t un = (~nibc) & 0xFu;
        if (un) {
            uint4 x = sp4[q];
            unsigned int vv[4] = {x.x, x.y, x.z, x.w};
            while (un) {
                int p = __ffs(un) - 1; un &= un - 1;
                int s = semf ? (int)__uint_as_float(vv[p]) : (int)vv[p];
                vals[p] = (s >= 0 && s < NSEM) ? s_sval[s]
                          : (unsigned int)__float_as_int(0.0f);
            }
        }
        op4[q] = make_uint4(vals[0], vals[1], vals[2], vals[3]);
    }
}

// ---------------- launch -----------------------------------------------------
extern "C" void kernel_launch(void* const* d_in, const int* in_sizes, int n_in,
                              void* d_out, int out_size) {
    const void* masks = nullptr;
    const void* sem   = nullptr;
    const void* smallA = nullptr;
    const void* smallB = nullptr;
    for (int i = 0; i < n_in; i++) {
        if (in_sizes[i] == MASK_ELEMS)      masks = d_in[i];
        else if (in_sizes[i] == SEM_ELEMS)  sem   = d_in[i];
        else if (in_sizes[i] == BB*NN) {
            if (!smallA) smallA = d_in[i]; else smallB = d_in[i];
        }
    }
    if (!masks)  masks  = d_in[0];
    if (!smallA) smallA = d_in[1];
    if (!smallB) smallB = d_in[2];
    if (!sem)    sem    = d_in[3];

    k_init<<<264, 256>>>();
    k_prep<<<1, 256>>>((const unsigned int*)smallA, (const unsigned int*)smallB,
                       (const unsigned int*)sem, (const unsigned int*)masks);
    // pack launched FIRST (rank-major grid: group 0 blocks retire first);
    // k_run overlaps by spinning on per-(b,g,x) pack counters.
    k_pack<<<dim3(WBLK, BB, NN), TPB>>>((const unsigned int*)masks);
    k_run<<<dim3(WBLK, BB), TPB>>>((const unsigned int*)sem, (uint4*)d_out);
}